// round 1
// baseline (speedup 1.0000x reference)
#include <cuda_runtime.h>
#include <cuda_bf16.h>
#include <math.h>

// ---------------- problem constants ----------------
#define N0C 1500000
#define N1C 200000
#define N2C 20000
#define BC  4096
#define E0C 2000000
#define E1C 200000
#define E2C 20480
#define DIN 100
#define DH  256
#define DOUT 47

// ---------------- device scratch (no allocs allowed) ----------------
__device__ int   g_cnt0[N1C];
__device__ int   g_off0[N1C + 1];
__device__ int   g_cur0[N1C];
__device__ int   g_csr0[E0C];
__device__ float g_mean0[(size_t)N1C * DIN];
__device__ float g_h0[(size_t)N1C * DH];

__device__ int   g_cnt1[N2C];
__device__ int   g_off1[N2C + 1];
__device__ int   g_cur1[N2C];
__device__ int   g_csr1[E1C];
__device__ float g_mean1[(size_t)N2C * DH];
__device__ float g_h1[(size_t)N2C * DH];

__device__ int   g_cnt2[BC];
__device__ int   g_off2[BC + 1];
__device__ int   g_cur2[BC];
__device__ int   g_csr2[E2C];
__device__ float g_mean2[(size_t)BC * DH];
__device__ float g_h2[(size_t)BC * DOUT];

// ---------------- CSR build ----------------
__global__ void k_hist(const int* __restrict__ dst, int E, int* __restrict__ cnt) {
    int i = blockIdx.x * blockDim.x + threadIdx.x;
    if (i < E) atomicAdd(&cnt[dst[i]], 1);
}

// single-block chunked exclusive scan (n up to a few hundred k)
__global__ void k_scan(const int* __restrict__ cnt, int n, int* __restrict__ off) {
    __shared__ int smem[1024];
    __shared__ int carry_s;
    int tid = threadIdx.x;
    if (tid == 0) carry_s = 0;
    __syncthreads();
    for (int base = 0; base < n; base += 1024) {
        int i = base + tid;
        int v = (i < n) ? cnt[i] : 0;
        smem[tid] = v;
        __syncthreads();
        #pragma unroll
        for (int ofs = 1; ofs < 1024; ofs <<= 1) {
            int add = (tid >= ofs) ? smem[tid - ofs] : 0;
            __syncthreads();
            smem[tid] += add;
            __syncthreads();
        }
        int incl = smem[tid];
        int carry = carry_s;
        if (i < n) off[i] = carry + incl - v;
        __syncthreads();
        if (tid == 1023) carry_s = carry + smem[1023];
        __syncthreads();
    }
    if (tid == 0) off[n] = carry_s;
}

__global__ void k_fill(const int* __restrict__ src, const int* __restrict__ dst, int E,
                       int* __restrict__ cur, int* __restrict__ csr) {
    int i = blockIdx.x * blockDim.x + threadIdx.x;
    if (i < E) {
        int p = atomicAdd(&cur[dst[i]], 1);
        csr[p] = src[i];
    }
}

// ---------------- segment mean: one warp per destination row ----------------
template<int D, int NR>
__global__ void k_agg(const float* __restrict__ X, const int* __restrict__ off,
                      const int* __restrict__ csr, int ndst, float* __restrict__ out) {
    int w = (blockIdx.x * blockDim.x + threadIdx.x) >> 5;
    if (w >= ndst) return;
    int lane = threadIdx.x & 31;
    int s = off[w], e = off[w + 1];
    float acc[NR];
    #pragma unroll
    for (int i = 0; i < NR; i++) acc[i] = 0.f;
    for (int j = s; j < e; j++) {
        const float* row = X + (size_t)csr[j] * D;
        #pragma unroll
        for (int i = 0; i < NR; i++) {
            int c = lane + 32 * i;
            if (c < D) acc[i] += row[c];
        }
    }
    float inv = (e > s) ? 1.0f / (float)(e - s) : 0.f;
    #pragma unroll
    for (int i = 0; i < NR; i++) {
        int c = lane + 32 * i;
        if (c < D) out[(size_t)w * D + c] = acc[i] * inv;
    }
}

// ---------------- fused dual-GEMM: C = act(A@Wa + B@Wb + bias) ----------------
// A,B: [M,K] row-major (same K & ld). Wa,Wb: [K,N] row-major. Treated as one
// GEMM with K2 = 2K (K2 % 8 == 0 for K=100 and K=256).
#define BM 128
#define BN 64
#define BK 8
template<int ACT>
__global__ __launch_bounds__(256)
void k_gemm2(const float* __restrict__ A, const float* __restrict__ Bm,
             const float* __restrict__ Wa, const float* __restrict__ Wb,
             const float* __restrict__ bias, float* __restrict__ C,
             int M, int K, int N) {
    __shared__ float As[BK][BM];
    __shared__ float Ws[BK][BN];
    int tid = threadIdx.x;
    int tx = tid & 15;       // N dir: 16 * 4 = 64
    int ty = tid >> 4;       // M dir: 16 * 8 = 128
    int m0 = blockIdx.y * BM;
    int n0 = blockIdx.x * BN;
    int K2 = 2 * K;

    float acc[8][4];
    #pragma unroll
    for (int i = 0; i < 8; i++)
        #pragma unroll
        for (int j = 0; j < 4; j++) acc[i][j] = 0.f;

    for (int kk0 = 0; kk0 < K2; kk0 += BK) {
        // A-tile 128x8: thread loads 4 scalars; row = tid/2, k = (tid&1)*4 + i
        int r = tid >> 1;
        int kbase = (tid & 1) * 4;
        #pragma unroll
        for (int i = 0; i < 4; i++) {
            int k2 = kk0 + kbase + i;
            int m = m0 + r;
            float v = 0.f;
            if (m < M) {
                v = (k2 < K) ? A[(size_t)m * K + k2]
                             : Bm[(size_t)m * K + (k2 - K)];
            }
            As[kbase + i][r] = v;
        }
        // W-tile 8x64: n = tid&63, k-row = tid>>6 and +4
        int wn = tid & 63;
        int wk = tid >> 6;   // 0..3
        #pragma unroll
        for (int i = 0; i < 2; i++) {
            int k2 = kk0 + wk + i * 4;
            int n = n0 + wn;
            float v = 0.f;
            if (n < N) {
                v = (k2 < K) ? Wa[(size_t)k2 * N + n]
                             : Wb[(size_t)(k2 - K) * N + n];
            }
            Ws[wk + i * 4][wn] = v;
        }
        __syncthreads();
        #pragma unroll
        for (int k = 0; k < BK; k++) {
            float a[8], w[4];
            #pragma unroll
            for (int i = 0; i < 8; i++) a[i] = As[k][ty * 8 + i];
            #pragma unroll
            for (int j = 0; j < 4; j++) w[j] = Ws[k][tx * 4 + j];
            #pragma unroll
            for (int i = 0; i < 8; i++)
                #pragma unroll
                for (int j = 0; j < 4; j++) acc[i][j] += a[i] * w[j];
        }
        __syncthreads();
    }
    #pragma unroll
    for (int i = 0; i < 8; i++) {
        int m = m0 + ty * 8 + i;
        if (m >= M) continue;
        #pragma unroll
        for (int j = 0; j < 4; j++) {
            int n = n0 + tx * 4 + j;
            if (n >= N) continue;
            float v = acc[i][j] + bias[n];
            if (ACT) v = fmaxf(v, 0.f);
            C[(size_t)m * N + n] = v;
        }
    }
}

// ---------------- log_softmax over 47 cols ----------------
__global__ void k_logsoftmax(const float* __restrict__ H, float* __restrict__ out,
                             int M, int N) {
    __shared__ float red[64];
    int row = blockIdx.x;
    int tid = threadIdx.x;
    float v = (tid < N) ? H[(size_t)row * N + tid] : -INFINITY;
    red[tid] = v;
    __syncthreads();
    #pragma unroll
    for (int s = 32; s > 0; s >>= 1) {
        if (tid < s) red[tid] = fmaxf(red[tid], red[tid + s]);
        __syncthreads();
    }
    float mx = red[0];
    __syncthreads();
    float e = (tid < N) ? expf(v - mx) : 0.f;
    red[tid] = e;
    __syncthreads();
    #pragma unroll
    for (int s = 32; s > 0; s >>= 1) {
        if (tid < s) red[tid] += red[tid + s];
        __syncthreads();
    }
    float lse = mx + logf(red[0]);
    if (tid < N) out[(size_t)row * N + tid] = v - lse;
}

// ---------------- host orchestration ----------------
static inline int ceil_div(int a, int b) { return (a + b - 1) / b; }

extern "C" void kernel_launch(void* const* d_in, const int* in_sizes, int n_in,
                              void* d_out, int out_size) {
    const float* x    = (const float*)d_in[0];
    const int*   src0 = (const int*)d_in[1];
    const int*   dst0 = (const int*)d_in[2];
    const int*   src1 = (const int*)d_in[3];
    const int*   dst1 = (const int*)d_in[4];
    const int*   src2 = (const int*)d_in[5];
    const int*   dst2 = (const int*)d_in[6];
    const float* Wl0  = (const float*)d_in[7];
    const float* Wr0  = (const float*)d_in[8];
    const float* b0   = (const float*)d_in[9];
    const float* Wl1  = (const float*)d_in[10];
    const float* Wr1  = (const float*)d_in[11];
    const float* b1   = (const float*)d_in[12];
    const float* Wl2  = (const float*)d_in[13];
    const float* Wr2  = (const float*)d_in[14];
    const float* b2   = (const float*)d_in[15];
    float* out = (float*)d_out;

    int E0 = in_sizes[1];
    int E1 = in_sizes[3];
    int E2 = in_sizes[5];

    void *cnt0, *off0, *cur0, *csr0, *mean0, *h0;
    void *cnt1, *off1, *cur1, *csr1, *mean1, *h1;
    void *cnt2, *off2, *cur2, *csr2, *mean2, *h2;
    cudaGetSymbolAddress(&cnt0, g_cnt0);  cudaGetSymbolAddress(&off0, g_off0);
    cudaGetSymbolAddress(&cur0, g_cur0);  cudaGetSymbolAddress(&csr0, g_csr0);
    cudaGetSymbolAddress(&mean0, g_mean0); cudaGetSymbolAddress(&h0, g_h0);
    cudaGetSymbolAddress(&cnt1, g_cnt1);  cudaGetSymbolAddress(&off1, g_off1);
    cudaGetSymbolAddress(&cur1, g_cur1);  cudaGetSymbolAddress(&csr1, g_csr1);
    cudaGetSymbolAddress(&mean1, g_mean1); cudaGetSymbolAddress(&h1, g_h1);
    cudaGetSymbolAddress(&cnt2, g_cnt2);  cudaGetSymbolAddress(&off2, g_off2);
    cudaGetSymbolAddress(&cur2, g_cur2);  cudaGetSymbolAddress(&csr2, g_csr2);
    cudaGetSymbolAddress(&mean2, g_mean2); cudaGetSymbolAddress(&h2, g_h2);

    // ---------- layer 0 ----------
    cudaMemsetAsync(cnt0, 0, (size_t)N1C * sizeof(int));
    k_hist<<<ceil_div(E0, 256), 256>>>(dst0, E0, (int*)cnt0);
    k_scan<<<1, 1024>>>((const int*)cnt0, N1C, (int*)off0);
    cudaMemcpyAsync(cur0, off0, (size_t)N1C * sizeof(int), cudaMemcpyDeviceToDevice);
    k_fill<<<ceil_div(E0, 256), 256>>>(src0, dst0, E0, (int*)cur0, (int*)csr0);
    k_agg<DIN, 4><<<ceil_div(N1C * 32, 256), 256>>>(
        x, (const int*)off0, (const int*)csr0, N1C, (float*)mean0);
    {
        dim3 grid(ceil_div(DH, BN), ceil_div(N1C, BM));
        k_gemm2<1><<<grid, 256>>>((const float*)mean0, x, Wl0, Wr0, b0,
                                  (float*)h0, N1C, DIN, DH);
    }

    // ---------- layer 1 ----------
    cudaMemsetAsync(cnt1, 0, (size_t)N2C * sizeof(int));
    k_hist<<<ceil_div(E1, 256), 256>>>(dst1, E1, (int*)cnt1);
    k_scan<<<1, 1024>>>((const int*)cnt1, N2C, (int*)off1);
    cudaMemcpyAsync(cur1, off1, (size_t)N2C * sizeof(int), cudaMemcpyDeviceToDevice);
    k_fill<<<ceil_div(E1, 256), 256>>>(src1, dst1, E1, (int*)cur1, (int*)csr1);
    k_agg<DH, 8><<<ceil_div(N2C * 32, 256), 256>>>(
        (const float*)h0, (const int*)off1, (const int*)csr1, N2C, (float*)mean1);
    {
        dim3 grid(ceil_div(DH, BN), ceil_div(N2C, BM));
        k_gemm2<1><<<grid, 256>>>((const float*)mean1, (const float*)h0, Wl1, Wr1, b1,
                                  (float*)h1, N2C, DH, DH);
    }

    // ---------- layer 2 ----------
    cudaMemsetAsync(cnt2, 0, (size_t)BC * sizeof(int));
    k_hist<<<ceil_div(E2, 256), 256>>>(dst2, E2, (int*)cnt2);
    k_scan<<<1, 1024>>>((const int*)cnt2, BC, (int*)off2);
    cudaMemcpyAsync(cur2, off2, (size_t)BC * sizeof(int), cudaMemcpyDeviceToDevice);
    k_fill<<<ceil_div(E2, 256), 256>>>(src2, dst2, E2, (int*)cur2, (int*)csr2);
    k_agg<DH, 8><<<ceil_div(BC * 32, 256), 256>>>(
        (const float*)h1, (const int*)off2, (const int*)csr2, BC, (float*)mean2);
    {
        dim3 grid(ceil_div(DOUT, BN), ceil_div(BC, BM));
        k_gemm2<0><<<grid, 256>>>((const float*)mean2, (const float*)h1, Wl2, Wr2, b2,
                                  (float*)h2, BC, DH, DOUT);
    }

    // ---------- log_softmax ----------
    k_logsoftmax<<<BC, 64>>>((const float*)h2, out, BC, DOUT);
}

// round 3
// speedup vs baseline: 1.8522x; 1.8522x over previous
#include <cuda_runtime.h>
#include <cuda_bf16.h>
#include <math.h>
#include <stdint.h>

// ---------------- problem constants ----------------
#define N0C 1500000
#define N1C 200000
#define N2C 20000
#define BC  4096
#define E0C 2000000
#define E1C 200000
#define E2C 20480
#define DIN 100
#define DH  256
#define DOUT 47

// ---------------- device scratch (no allocs allowed) ----------------
__device__ int   g_cnt0[N1C];
__device__ int   g_off0[N1C + 1];
__device__ int   g_cur0[N1C];
__device__ int   g_csr0[E0C];
__device__ int   g_cnt1[N2C];
__device__ int   g_off1[N2C + 1];
__device__ int   g_cur1[N2C];
__device__ int   g_csr1[E1C];
__device__ int   g_cnt2[BC];
__device__ int   g_off2[BC + 1];
__device__ int   g_cur2[BC];
__device__ int   g_csr2[E2C];
__device__ int   g_blksum[256];
__device__ int   g_blkoff[257];

// packed bf16 A matrices: [M, 2*K2P]  ([hi-region | lo-region]; pads stay 0)
__device__ __nv_bfloat16 g_Apk0[(size_t)N1C * 512];   // K2P=256
__device__ __nv_bfloat16 g_Apk1[(size_t)N2C * 1024];  // K2P=512
// packed bf16 B matrices (K-major, B[n,k]): [256, 3*K2P] = [Whi | Wlo | Whi]
__device__ __nv_bfloat16 g_Bpk0[(size_t)256 * 768];
__device__ __nv_bfloat16 g_Bpk1[(size_t)256 * 1536];

__device__ float g_h0[(size_t)N1C * DH];
__device__ float g_h1[(size_t)N2C * DH];
__device__ float g_mean2[(size_t)BC * DH];
__device__ float g_h2[(size_t)BC * DOUT];

// ---------------- CSR build ----------------
__global__ void k_hist(const int* __restrict__ dst, int E, int* __restrict__ cnt) {
    int i = blockIdx.x * blockDim.x + threadIdx.x;
    if (i < E) atomicAdd(&cnt[dst[i]], 1);
}

// decoupled 3-kernel scan
__global__ void k_scan_blk(const int* __restrict__ cnt, int n,
                           int* __restrict__ off, int* __restrict__ blksum) {
    __shared__ int wsum[32];
    int tid = threadIdx.x, lane = tid & 31, wid = tid >> 5;
    int i = blockIdx.x * 1024 + tid;
    int v = (i < n) ? cnt[i] : 0;
    int x = v;
    #pragma unroll
    for (int o = 1; o < 32; o <<= 1) {
        int y = __shfl_up_sync(0xFFFFFFFFu, x, o);
        if (lane >= o) x += y;
    }
    if (lane == 31) wsum[wid] = x;
    __syncthreads();
    if (wid == 0) {
        int s = wsum[lane];
        #pragma unroll
        for (int o = 1; o < 32; o <<= 1) {
            int y = __shfl_up_sync(0xFFFFFFFFu, s, o);
            if (lane >= o) s += y;
        }
        wsum[lane] = s;
    }
    __syncthreads();
    int base = wid ? wsum[wid - 1] : 0;
    int incl = base + x;
    if (i < n) off[i] = incl - v;
    if (tid == 1023) blksum[blockIdx.x] = incl;
}

__global__ void k_scan_tops(const int* __restrict__ blksum, int nb,
                            int* __restrict__ blkoff, int* __restrict__ off, int n) {
    __shared__ int wsum[8];
    int tid = threadIdx.x, lane = tid & 31, wid = tid >> 5;  // 256 threads
    int v = (tid < nb) ? blksum[tid] : 0;
    int x = v;
    #pragma unroll
    for (int o = 1; o < 32; o <<= 1) {
        int y = __shfl_up_sync(0xFFFFFFFFu, x, o);
        if (lane >= o) x += y;
    }
    if (lane == 31) wsum[wid] = x;
    __syncthreads();
    if (tid == 0) {
        int run = 0;
        #pragma unroll
        for (int w = 0; w < 8; w++) { int t = wsum[w]; wsum[w] = run; run += t; }
        off[n] = run;
    }
    __syncthreads();
    int incl = wsum[wid] + x;
    if (tid < nb) blkoff[tid] = incl - v;
}

__global__ void k_scan_add(int* __restrict__ off, int n, const int* __restrict__ blkoff) {
    int i = blockIdx.x * 1024 + threadIdx.x;
    if (i < n) off[i] += blkoff[blockIdx.x];
}

__global__ void k_fill(const int* __restrict__ src, const int* __restrict__ dst, int E,
                       int* __restrict__ cur, int* __restrict__ csr) {
    int i = blockIdx.x * blockDim.x + threadIdx.x;
    if (i < E) {
        int p = atomicAdd(&cur[dst[i]], 1);
        csr[p] = src[i];
    }
}

// ---------------- segment mean -> bf16 hi/lo into packed A ----------------
template<int D, int NR, int K2P>
__global__ void k_agg_hl(const float* __restrict__ X, const int* __restrict__ off,
                         const int* __restrict__ csr, int ndst, __nv_bfloat16* __restrict__ out) {
    int w = (blockIdx.x * blockDim.x + threadIdx.x) >> 5;
    if (w >= ndst) return;
    int lane = threadIdx.x & 31;
    int s = off[w], e = off[w + 1];
    float acc[NR];
    #pragma unroll
    for (int i = 0; i < NR; i++) acc[i] = 0.f;
    for (int j = s; j < e; j++) {
        const float* row = X + (size_t)csr[j] * D;
        #pragma unroll
        for (int i = 0; i < NR; i++) {
            int c = lane + 32 * i;
            if (c < D) acc[i] += __ldg(row + c);
        }
    }
    float inv = (e > s) ? 1.0f / (float)(e - s) : 0.f;
    size_t base = (size_t)w * (2 * K2P);
    #pragma unroll
    for (int i = 0; i < NR; i++) {
        int c = lane + 32 * i;
        if (c < D) {
            float v = acc[i] * inv;
            __nv_bfloat16 h = __float2bfloat16_rn(v);
            float lo = v - __bfloat162float(h);
            out[base + c]       = h;
            out[base + K2P + c] = __float2bfloat16_rn(lo);
        }
    }
}

// fp32 mean for layer 2
template<int D, int NR>
__global__ void k_agg(const float* __restrict__ X, const int* __restrict__ off,
                      const int* __restrict__ csr, int ndst, float* __restrict__ out) {
    int w = (blockIdx.x * blockDim.x + threadIdx.x) >> 5;
    if (w >= ndst) return;
    int lane = threadIdx.x & 31;
    int s = off[w], e = off[w + 1];
    float acc[NR];
    #pragma unroll
    for (int i = 0; i < NR; i++) acc[i] = 0.f;
    for (int j = s; j < e; j++) {
        const float* row = X + (size_t)csr[j] * D;
        #pragma unroll
        for (int i = 0; i < NR; i++) {
            int c = lane + 32 * i;
            if (c < D) acc[i] += row[c];
        }
    }
    float inv = (e > s) ? 1.0f / (float)(e - s) : 0.f;
    #pragma unroll
    for (int i = 0; i < NR; i++) {
        int c = lane + 32 * i;
        if (c < D) out[(size_t)w * D + c] = acc[i] * inv;
    }
}

// fp32 -> bf16 hi/lo converter for the x_dst part (writes cols [COFF, COFF+D))
template<int D, int K2P, int COFF>
__global__ void k_conv_hl(const float* __restrict__ X, int M, __nv_bfloat16* __restrict__ out) {
    int i = blockIdx.x * blockDim.x + threadIdx.x;
    if (i >= M * D) return;
    int m = i / D, c = i % D;
    float v = X[i];
    __nv_bfloat16 h = __float2bfloat16_rn(v);
    float lo = v - __bfloat162float(h);
    size_t base = (size_t)m * (2 * K2P);
    out[base + COFF + c]       = h;
    out[base + K2P + COFF + c] = __float2bfloat16_rn(lo);
}

// weight pack: B[n, k3] for k3 in [0, 3*K2P): regions [Whi | Wlo | Whi]
template<int K2P, int KL>
__global__ void k_packW(const float* __restrict__ Wl, const float* __restrict__ Wr,
                        __nv_bfloat16* __restrict__ out) {
    int i = blockIdx.x * blockDim.x + threadIdx.x;
    const int KW = 3 * K2P;
    if (i >= 256 * KW) return;
    int n = i / KW, k3 = i % KW;
    int region = k3 / K2P, kk = k3 % K2P;
    float v = 0.f;
    if (kk < KL) v = Wl[(size_t)kk * 256 + n];
    else if (kk < 2 * KL) v = Wr[(size_t)(kk - KL) * 256 + n];
    __nv_bfloat16 h = __float2bfloat16_rn(v);
    __nv_bfloat16 res = (region == 1) ? __float2bfloat16_rn(v - __bfloat162float(h)) : h;
    out[(size_t)n * KW + k3] = res;
}

// ---------------- mma.sync bf16 GEMM: C[M,256] = relu(Apk @ Bpk^T + bias) ----------------
// Apk: [M, KA] bf16 row-major (KA = 2*K2P, regions [hi|lo]).
// Bpk: [256, KW] bf16 row-major (KW = 3*K2P, regions [Whi|Wlo|Whi], K-major B).
// K-chunks of 64: chunk c uses A cols acol(c) where region = c/NCH_R:
//   region 0: A hi x W hi, region 1: A hi x W lo, region 2: A lo x W hi.
// Block: 256 threads / 8 warps; tile 128(M) x 128(N); warp = 32x64 via 2x8 m16n8k16.

__device__ __forceinline__ void mma_bf16_16816(float* d, const uint32_t* a, const uint32_t* b) {
    asm volatile(
        "mma.sync.aligned.m16n8k16.row.col.f32.bf16.bf16.f32 "
        "{%0,%1,%2,%3}, {%4,%5,%6,%7}, {%8,%9}, {%0,%1,%2,%3};"
        : "+f"(d[0]), "+f"(d[1]), "+f"(d[2]), "+f"(d[3])
        : "r"(a[0]), "r"(a[1]), "r"(a[2]), "r"(a[3]), "r"(b[0]), "r"(b[1]));
}

#define ASTRIDE 72   // bf16 elems per smem row (64 + 8 pad) -> 144B, 4-bank stagger

template<int NCH_R, int ACT>
__global__ __launch_bounds__(256)
void k_mma(const __nv_bfloat16* __restrict__ Apk, const __nv_bfloat16* __restrict__ Bpk,
           const float* __restrict__ bias, float* __restrict__ C, int M, int KA, int KW) {
    constexpr int NCH = 3 * NCH_R;
    __shared__ __nv_bfloat16 As[128][ASTRIDE];
    __shared__ __nv_bfloat16 Bs[128][ASTRIDE];

    int tid = threadIdx.x;
    int wid = tid >> 5;
    int lane = tid & 31;
    int g = lane >> 2;          // groupID
    int tg = lane & 3;          // thread in group
    int warp_m = wid & 3;       // 0..3 -> rows warp_m*32
    int warp_n = wid >> 2;      // 0..1 -> cols warp_n*64
    int m0 = blockIdx.x * 128;
    int n0 = blockIdx.y * 128;

    float acc[2][8][4];
    #pragma unroll
    for (int mt = 0; mt < 2; mt++)
        #pragma unroll
        for (int nt = 0; nt < 8; nt++)
            #pragma unroll
            for (int j = 0; j < 4; j++) acc[mt][nt][j] = 0.f;

    for (int c = 0; c < NCH; c++) {
        int region = c / NCH_R;
        int r = c - region * NCH_R;
        int acol = ((region < 2) ? r : (NCH_R + r)) * 64;
        int wcol = c * 64;

        // load A tile: 128 rows x 64 bf16 (128B/row), 4 uint4 per thread
        #pragma unroll
        for (int i = 0; i < 4; i++) {
            int e = tid + i * 256;
            int row = e >> 3, q = e & 7;
            uint4 v = make_uint4(0u, 0u, 0u, 0u);
            if (m0 + row < M)
                v = *(const uint4*)(Apk + (size_t)(m0 + row) * KA + acol + q * 8);
            *(uint4*)(&As[row][q * 8]) = v;
        }
        // load B tile: 128 rows (n) x 64 bf16
        #pragma unroll
        for (int i = 0; i < 4; i++) {
            int e = tid + i * 256;
            int row = e >> 3, q = e & 7;
            uint4 v = *(const uint4*)(Bpk + (size_t)(n0 + row) * KW + wcol + q * 8);
            *(uint4*)(&Bs[row][q * 8]) = v;
        }
        __syncthreads();

        #pragma unroll
        for (int ks = 0; ks < 4; ks++) {
            int kb = ks * 16;
            uint32_t af[2][4];
            #pragma unroll
            for (int mt = 0; mt < 2; mt++) {
                int wr = warp_m * 32 + mt * 16;
                af[mt][0] = *(const uint32_t*)(&As[wr + g][kb + tg * 2]);
                af[mt][1] = *(const uint32_t*)(&As[wr + g + 8][kb + tg * 2]);
                af[mt][2] = *(const uint32_t*)(&As[wr + g][kb + tg * 2 + 8]);
                af[mt][3] = *(const uint32_t*)(&As[wr + g + 8][kb + tg * 2 + 8]);
            }
            uint32_t bf[8][2];
            #pragma unroll
            for (int nt = 0; nt < 8; nt++) {
                int nb = warp_n * 64 + nt * 8;
                bf[nt][0] = *(const uint32_t*)(&Bs[nb + g][kb + tg * 2]);
                bf[nt][1] = *(const uint32_t*)(&Bs[nb + g][kb + tg * 2 + 8]);
            }
            #pragma unroll
            for (int mt = 0; mt < 2; mt++)
                #pragma unroll
                for (int nt = 0; nt < 8; nt++)
                    mma_bf16_16816(acc[mt][nt], af[mt], bf[nt]);
        }
        __syncthreads();
    }

    // epilogue: bias + (relu) + store fp32
    #pragma unroll
    for (int mt = 0; mt < 2; mt++) {
        int row0 = m0 + warp_m * 32 + mt * 16 + g;
        #pragma unroll
        for (int nt = 0; nt < 8; nt++) {
            int col = n0 + warp_n * 64 + nt * 8 + tg * 2;
            float bx = bias[col], by = bias[col + 1];
            if (row0 < M) {
                float2 o;
                o.x = acc[mt][nt][0] + bx;
                o.y = acc[mt][nt][1] + by;
                if (ACT) { o.x = fmaxf(o.x, 0.f); o.y = fmaxf(o.y, 0.f); }
                *(float2*)(C + (size_t)row0 * 256 + col) = o;
            }
            if (row0 + 8 < M) {
                float2 o;
                o.x = acc[mt][nt][2] + bx;
                o.y = acc[mt][nt][3] + by;
                if (ACT) { o.x = fmaxf(o.x, 0.f); o.y = fmaxf(o.y, 0.f); }
                *(float2*)(C + (size_t)(row0 + 8) * 256 + col) = o;
            }
        }
    }
}

// ---------------- SIMT fp32 dual-GEMM for tiny layer 2 ----------------
#define BM 128
#define BN 64
#define BK 8
template<int ACT>
__global__ __launch_bounds__(256)
void k_gemm2(const float* __restrict__ A, const float* __restrict__ Bm,
             const float* __restrict__ Wa, const float* __restrict__ Wb,
             const float* __restrict__ bias, float* __restrict__ C,
             int M, int K, int N) {
    __shared__ float Asm[BK][BM];
    __shared__ float Ws[BK][BN];
    int tid = threadIdx.x;
    int tx = tid & 15;
    int ty = tid >> 4;
    int m0 = blockIdx.y * BM;
    int n0 = blockIdx.x * BN;
    int K2 = 2 * K;

    float acc[8][4];
    #pragma unroll
    for (int i = 0; i < 8; i++)
        #pragma unroll
        for (int j = 0; j < 4; j++) acc[i][j] = 0.f;

    for (int kk0 = 0; kk0 < K2; kk0 += BK) {
        int r = tid >> 1;
        int kbase = (tid & 1) * 4;
        #pragma unroll
        for (int i = 0; i < 4; i++) {
            int k2 = kk0 + kbase + i;
            int m = m0 + r;
            float v = 0.f;
            if (m < M) v = (k2 < K) ? A[(size_t)m * K + k2] : Bm[(size_t)m * K + (k2 - K)];
            Asm[kbase + i][r] = v;
        }
        int wn = tid & 63;
        int wk = tid >> 6;
        #pragma unroll
        for (int i = 0; i < 2; i++) {
            int k2 = kk0 + wk + i * 4;
            int n = n0 + wn;
            float v = 0.f;
            if (n < N) v = (k2 < K) ? Wa[(size_t)k2 * N + n] : Wb[(size_t)(k2 - K) * N + n];
            Ws[wk + i * 4][wn] = v;
        }
        __syncthreads();
        #pragma unroll
        for (int k = 0; k < BK; k++) {
            float a[8], w[4];
            #pragma unroll
            for (int i = 0; i < 8; i++) a[i] = Asm[k][ty * 8 + i];
            #pragma unroll
            for (int j = 0; j < 4; j++) w[j] = Ws[k][tx * 4 + j];
            #pragma unroll
            for (int i = 0; i < 8; i++)
                #pragma unroll
                for (int j = 0; j < 4; j++) acc[i][j] += a[i] * w[j];
        }
        __syncthreads();
    }
    #pragma unroll
    for (int i = 0; i < 8; i++) {
        int m = m0 + ty * 8 + i;
        if (m >= M) continue;
        #pragma unroll
        for (int j = 0; j < 4; j++) {
            int n = n0 + tx * 4 + j;
            if (n >= N) continue;
            float v = acc[i][j] + bias[n];
            if (ACT) v = fmaxf(v, 0.f);
            C[(size_t)m * N + n] = v;
        }
    }
}

// ---------------- log_softmax over 47 cols ----------------
__global__ void k_logsoftmax(const float* __restrict__ H, float* __restrict__ out,
                             int M, int N) {
    __shared__ float red[64];
    int row = blockIdx.x;
    int tid = threadIdx.x;
    float v = (tid < N) ? H[(size_t)row * N + tid] : -INFINITY;
    red[tid] = v;
    __syncthreads();
    #pragma unroll
    for (int s = 32; s > 0; s >>= 1) {
        if (tid < s) red[tid] = fmaxf(red[tid], red[tid + s]);
        __syncthreads();
    }
    float mx = red[0];
    __syncthreads();
    float e = (tid < N) ? expf(v - mx) : 0.f;
    red[tid] = e;
    __syncthreads();
    #pragma unroll
    for (int s = 32; s > 0; s >>= 1) {
        if (tid < s) red[tid] += red[tid + s];
        __syncthreads();
    }
    float lse = mx + logf(red[0]);
    if (tid < N) out[(size_t)row * N + tid] = v - lse;
}

// ---------------- host orchestration ----------------
static inline int ceil_div(int a, int b) { return (a + b - 1) / b; }

static void build_csr(const int* src, const int* dst, int E, int n,
                      void* cnt, void* off, void* cur, void* csr,
                      void* blksum, void* blkoff) {
    cudaMemsetAsync(cnt, 0, (size_t)n * sizeof(int));
    k_hist<<<ceil_div(E, 256), 256>>>(dst, E, (int*)cnt);
    int nb = ceil_div(n, 1024);
    k_scan_blk<<<nb, 1024>>>((const int*)cnt, n, (int*)off, (int*)blksum);
    k_scan_tops<<<1, 256>>>((const int*)blksum, nb, (int*)blkoff, (int*)off, n);
    k_scan_add<<<nb, 1024>>>((int*)off, n, (const int*)blkoff);
    cudaMemcpyAsync(cur, off, (size_t)n * sizeof(int), cudaMemcpyDeviceToDevice);
    k_fill<<<ceil_div(E, 256), 256>>>(src, dst, E, (int*)cur, (int*)csr);
}

extern "C" void kernel_launch(void* const* d_in, const int* in_sizes, int n_in,
                              void* d_out, int out_size) {
    const float* x    = (const float*)d_in[0];
    const int*   src0 = (const int*)d_in[1];
    const int*   dst0 = (const int*)d_in[2];
    const int*   src1 = (const int*)d_in[3];
    const int*   dst1 = (const int*)d_in[4];
    const int*   src2 = (const int*)d_in[5];
    const int*   dst2 = (const int*)d_in[6];
    const float* Wl0  = (const float*)d_in[7];
    const float* Wr0  = (const float*)d_in[8];
    const float* b0   = (const float*)d_in[9];
    const float* Wl1  = (const float*)d_in[10];
    const float* Wr1  = (const float*)d_in[11];
    const float* b1   = (const float*)d_in[12];
    const float* Wl2  = (const float*)d_in[13];
    const float* Wr2  = (const float*)d_in[14];
    const float* b2   = (const float*)d_in[15];
    float* out = (float*)d_out;

    int E0 = in_sizes[1];
    int E1 = in_sizes[3];
    int E2 = in_sizes[5];

    void *cnt0, *off0, *cur0, *csr0, *cnt1, *off1, *cur1, *csr1;
    void *cnt2, *off2, *cur2, *csr2, *blksum, *blkoff;
    void *Apk0, *Bpk0, *Apk1, *Bpk1, *h0, *h1, *mean2, *h2;
    cudaGetSymbolAddress(&cnt0, g_cnt0);  cudaGetSymbolAddress(&off0, g_off0);
    cudaGetSymbolAddress(&cur0, g_cur0);  cudaGetSymbolAddress(&csr0, g_csr0);
    cudaGetSymbolAddress(&cnt1, g_cnt1);  cudaGetSymbolAddress(&off1, g_off1);
    cudaGetSymbolAddress(&cur1, g_cur1);  cudaGetSymbolAddress(&csr1, g_csr1);
    cudaGetSymbolAddress(&cnt2, g_cnt2);  cudaGetSymbolAddress(&off2, g_off2);
    cudaGetSymbolAddress(&cur2, g_cur2);  cudaGetSymbolAddress(&csr2, g_csr2);
    cudaGetSymbolAddress(&blksum, g_blksum); cudaGetSymbolAddress(&blkoff, g_blkoff);
    cudaGetSymbolAddress(&Apk0, g_Apk0);  cudaGetSymbolAddress(&Bpk0, g_Bpk0);
    cudaGetSymbolAddress(&Apk1, g_Apk1);  cudaGetSymbolAddress(&Bpk1, g_Bpk1);
    cudaGetSymbolAddress(&h0, g_h0);      cudaGetSymbolAddress(&h1, g_h1);
    cudaGetSymbolAddress(&mean2, g_mean2); cudaGetSymbolAddress(&h2, g_h2);

    // ---------- layer 0 ----------
    build_csr(src0, dst0, E0, N1C, cnt0, off0, cur0, csr0, blksum, blkoff);
    k_agg_hl<DIN, 4, 256><<<ceil_div(N1C * 32, 256), 256>>>(
        x, (const int*)off0, (const int*)csr0, N1C, (__nv_bfloat16*)Apk0);
    k_conv_hl<DIN, 256, DIN><<<ceil_div(N1C * DIN, 256), 256>>>(
        x, N1C, (__nv_bfloat16*)Apk0);
    k_packW<256, DIN><<<ceil_div(256 * 768, 256), 256>>>(Wl0, Wr0, (__nv_bfloat16*)Bpk0);
    {
        dim3 grid(ceil_div(N1C, 128), 2);
        k_mma<4, 1><<<grid, 256>>>((const __nv_bfloat16*)Apk0, (const __nv_bfloat16*)Bpk0,
                                   b0, (float*)h0, N1C, 512, 768);
    }

    // ---------- layer 1 ----------
    build_csr(src1, dst1, E1, N2C, cnt1, off1, cur1, csr1, blksum, blkoff);
    k_agg_hl<DH, 8, 512><<<ceil_div(N2C * 32, 256), 256>>>(
        (const float*)h0, (const int*)off1, (const int*)csr1, N2C, (__nv_bfloat16*)Apk1);
    k_conv_hl<DH, 512, DH><<<ceil_div(N2C * DH, 256), 256>>>(
        (const float*)h0, N2C, (__nv_bfloat16*)Apk1);
    k_packW<512, DH><<<ceil_div(256 * 1536, 256), 256>>>(Wl1, Wr1, (__nv_bfloat16*)Bpk1);
    {
        dim3 grid(ceil_div(N2C, 128), 2);
        k_mma<8, 1><<<grid, 256>>>((const __nv_bfloat16*)Apk1, (const __nv_bfloat16*)Bpk1,
                                   b1, (float*)h1, N2C, 1024, 1536);
    }

    // ---------- layer 2 (tiny, SIMT fp32) ----------
    build_csr(src2, dst2, E2, BC, cnt2, off2, cur2, csr2, blksum, blkoff);
    k_agg<DH, 8><<<ceil_div(BC * 32, 256), 256>>>(
        (const float*)h1, (const int*)off2, (const int*)csr2, BC, (float*)mean2);
    {
        dim3 grid(ceil_div(DOUT, BN), ceil_div(BC, BM));
        k_gemm2<0><<<grid, 256>>>((const float*)mean2, (const float*)h1, Wl2, Wr2, b2,
                                  (float*)h2, BC, DH, DOUT);
    }

    // ---------- log_softmax ----------
    k_logsoftmax<<<BC, 64>>>((const float*)h2, out, BC, DOUT);
}